// round 8
// baseline (speedup 1.0000x reference)
#include <cuda_runtime.h>
#include <cuda_bf16.h>
#include <stdint.h>

#define NN 100000
#define NE 1600000
#define HID 128

#define SCHUNK 512
#define NCHUNK ((NN + SCHUNK - 1) / SCHUNK)

// ---------------- device scratch ----------------
__device__ int   g_src[NE];
__device__ int   g_dst[NE];
__device__ float g_dis[NN];            // deg (init 1.0 self-loop), then rsqrt(deg)
__device__ int   g_cursor[NN];         // in-degree count, then CSR fill cursor
__device__ int   g_rowptr[NN + 1];
__device__ int   g_csrsrc[NE];
__device__ float g_csrcoef[NE];
__device__ float g_a1[NN];             // layer-1 scalar aggregation
__device__ __align__(16) float g_h1[(size_t)NN * HID];
__device__ __align__(16) float g_agg[(size_t)NN * HID];
__device__ int   g_ticket;
__device__ int   g_state[NCHUNK];      // scan lookback: 0 = pending, else total+1

// ---------------- packed fp32x2 helpers ----------------
__device__ __forceinline__ unsigned long long pk2(float lo, float hi) {
    unsigned long long r;
    asm("mov.b64 %0, {%1,%2};" : "=l"(r) : "f"(lo), "f"(hi));
    return r;
}
__device__ __forceinline__ unsigned long long ffma2(unsigned long long a,
                                                    unsigned long long b,
                                                    unsigned long long c) {
    unsigned long long d;
    asm("fma.rn.f32x2 %0, %1, %2, %3;" : "=l"(d) : "l"(a), "l"(b), "l"(c));
    return d;
}
__device__ __forceinline__ void upk2(unsigned long long v, float& lo, float& hi) {
    asm("mov.b64 {%0,%1}, %2;" : "=f"(lo), "=f"(hi) : "l"(v));
}

// ---------------- K1: init ----------------
__global__ void k_init(void) {
    int i = blockIdx.x * blockDim.x + threadIdx.x;
    if (i < NN) { g_dis[i] = 1.0f; g_cursor[i] = 0; g_a1[i] = 0.f; }
    if (i < NCHUNK) g_state[i] = 0;
    if (i == 0) g_ticket = 0;
}

// ---------------- K2: convert (inline dtype detect) + degree ----------------
__global__ void k_conv_deg(const void* ei, const float* __restrict__ w) {
    __shared__ int sflag;
    int t = threadIdx.x;
    if (t < 32) {
        const long long* p = (const long long*)ei;
        long long v = p[(long long)t * (NE / 32)];
        bool ok = (v >= 0 && v < NN);
        unsigned m = __ballot_sync(0xFFFFFFFFu, ok);
        if (t == 0) sflag = (m == 0xFFFFFFFFu) ? 1 : 0;
    }
    __syncthreads();
    int e = blockIdx.x * blockDim.x + t;
    if (e >= NE) return;
    int s, d;
    if (sflag) {
        const long long* p = (const long long*)ei;
        s = (int)p[e]; d = (int)p[e + NE];
    } else {
        const int* p = (const int*)ei;
        s = p[e]; d = p[e + NE];
    }
    g_src[e] = s; g_dst[e] = d;
    atomicAdd(&g_dis[d], w[e]);
    atomicAdd(&g_cursor[d], 1);
}

// ---------------- K3: single-pass scan (decoupled lookback) + rsqrt ----------
__global__ void k_scan(void) {       // <<<NCHUNK, SCHUNK>>>
    __shared__ int sh[SCHUNK];
    __shared__ int sbid, soff;
    int t = threadIdx.x;
    if (t == 0) sbid = atomicAdd(&g_ticket, 1);
    __syncthreads();
    int bid = sbid;
    int idx = bid * SCHUNK + t;
    int v = (idx < NN) ? g_cursor[idx] : 0;
    sh[t] = v;
    __syncthreads();
    for (int off = 1; off < SCHUNK; off <<= 1) {
        int u = (t >= off) ? sh[t - off] : 0;
        __syncthreads();
        sh[t] += u;
        __syncthreads();
    }
    if (t == 0) atomicExch(&g_state[bid], sh[SCHUNK - 1] + 1);  // publish total
    if (t < 32) {                                                // lookback
        int acc = 0;
        for (int b = t; b < bid; b += 32) {
            int s;
            while ((s = atomicAdd(&g_state[b], 0)) == 0) {}
            acc += s - 1;
        }
        #pragma unroll
        for (int o = 16; o; o >>= 1) acc += __shfl_xor_sync(0xFFFFFFFFu, acc, o);
        if (t == 0) soff = acc;
    }
    __syncthreads();
    if (idx < NN) {
        int r = sh[t] - v + soff;     // exclusive global scan
        g_rowptr[idx] = r;
        g_cursor[idx] = r;
        g_dis[idx] = rsqrtf(g_dis[idx]);
    }
    if (bid == 0 && t == 0) g_rowptr[NN] = NE;
}

// ---------------- K4: CSR fill + layer-1 scalar aggregation -------------------
__global__ void k_fill(const float* __restrict__ w, const float* __restrict__ x) {
    int e = blockIdx.x * blockDim.x + threadIdx.x;
    if (e >= NE) return;
    int d = g_dst[e], s = g_src[e];
    float c = g_dis[s] * w[e] * g_dis[d];
    int pos = atomicAdd(&g_cursor[d], 1);
    g_csrsrc[pos]  = s;
    g_csrcoef[pos] = c;
    atomicAdd(&g_a1[d], c * __ldg(&x[s]));
}

// ---------------- K5: expand scalar a1 -> h1 (warp per node) ------------------
__global__ void k_expand(const float* __restrict__ x,
                         const float* __restrict__ W1,
                         const float* __restrict__ b1) {
    int gt = blockIdx.x * blockDim.x + threadIdx.x;
    int node = gt >> 5, lane = gt & 31;
    if (node >= NN) return;
    float dd = g_dis[node];
    float a  = g_a1[node] + dd * dd * x[node];
    size_t base = (size_t)node * HID;
    #pragma unroll
    for (int k = 0; k < 4; k++) {
        int f = lane + 32 * k;
        g_h1[base + f] = fmaxf(fmaf(a, W1[f], b1[f]), 0.f);
    }
}

// ---------------- K6: layer-2 SpMM, warp per node, float4 + shfl --------------
__global__ void k_agg(void) {        // <<<(NN+7)/8, 256>>>
    int warp = threadIdx.x >> 5, lane = threadIdx.x & 31;
    int node = blockIdx.x * 8 + warp;
    if (node >= NN) return;
    const float4* __restrict__ h4 = (const float4*)g_h1;
    float dd = g_dis[node];
    float s2 = dd * dd;
    float4 v = h4[(size_t)node * 32 + lane];
    float4 acc = make_float4(s2 * v.x, s2 * v.y, s2 * v.z, s2 * v.w);
    int s0 = g_rowptr[node], s1 = g_rowptr[node + 1];
    for (int base = s0; base < s1; base += 32) {
        int j = base + lane;
        int ss = 0; float cc = 0.f;
        if (j < s1) { ss = g_csrsrc[j]; cc = g_csrcoef[j]; }
        int m = s1 - base;
        if (m >= 32) {
            // full batch: static trip count -> unrolled, front-batched LDG.128s
            #pragma unroll 4
            for (int k = 0; k < 32; k++) {
                int   sn = __shfl_sync(0xFFFFFFFFu, ss, k);
                float cf = __shfl_sync(0xFFFFFFFFu, cc, k);
                float4 hv = h4[(size_t)sn * 32 + lane];
                acc.x = fmaf(cf, hv.x, acc.x);
                acc.y = fmaf(cf, hv.y, acc.y);
                acc.z = fmaf(cf, hv.z, acc.z);
                acc.w = fmaf(cf, hv.w, acc.w);
            }
        } else {
            for (int k = 0; k < m; k++) {
                int   sn = __shfl_sync(0xFFFFFFFFu, ss, k);
                float cf = __shfl_sync(0xFFFFFFFFu, cc, k);
                float4 hv = h4[(size_t)sn * 32 + lane];
                acc.x = fmaf(cf, hv.x, acc.x);
                acc.y = fmaf(cf, hv.y, acc.y);
                acc.z = fmaf(cf, hv.z, acc.z);
                acc.w = fmaf(cf, hv.w, acc.w);
            }
        }
    }
    ((float4*)g_agg)[(size_t)node * 32 + lane] = acc;
}

// ---------------- K7: fused MLP head, packed f32x2 ----------------------------
#define NT  16
#define NTP 18   // +2 pad: kills bank conflicts, keeps 8B alignment
__global__ __launch_bounds__(256) void k_mlp(
        const float* __restrict__ W2,  const float* __restrict__ b2,
        const float* __restrict__ Wl1, const float* __restrict__ bl1,
        const float* __restrict__ Wl2, const float* __restrict__ bl2,
        float* __restrict__ out) {     // <<<ceil(NN/NT), 256>>>
    __shared__ __align__(16) float vshT[HID][NTP];       // transposed agg tile
    __shared__ __align__(16) float h2T[2 * HID][NTP];    // transposed h2
    __shared__ __align__(16) float h3sh[NT][HID];
    int base = blockIdx.x * NT;
    int t = threadIdx.x;

    for (int i = t; i < NT * HID; i += 256) {
        int n = i >> 7, f = i & 127;
        int node = base + n;
        vshT[f][n] = (node < NN) ? g_agg[(size_t)node * HID + f] : 0.f;
    }
    __syncthreads();

    // phase 1: h2[c=t] = relu(sum_f agg[n][f] * W2[f][c] + b2[c]), node-pairs packed
    {
        float bb = b2[t];
        unsigned long long acc[NT / 2];
        unsigned long long bp = pk2(bb, bb);
        #pragma unroll
        for (int i = 0; i < NT / 2; i++) acc[i] = bp;
        #pragma unroll 2
        for (int f = 0; f < HID; f++) {
            float wf = W2[f * 256 + t];
            unsigned long long wp = pk2(wf, wf);
            const unsigned long long* row = (const unsigned long long*)&vshT[f][0];
            #pragma unroll
            for (int i = 0; i < NT / 2; i++) acc[i] = ffma2(row[i], wp, acc[i]);
        }
        #pragma unroll
        for (int i = 0; i < NT / 2; i++) {
            float lo, hi; upk2(acc[i], lo, hi);
            h2T[t][2 * i]     = fmaxf(lo, 0.f);
            h2T[t][2 * i + 1] = fmaxf(hi, 0.f);
        }
    }
    __syncthreads();

    // phase 2: h3[g] = relu(sum_c h2[n][c] * Wl1[c][g] + bl1[g]); 2 halves x 8 nodes
    {
        int g = t & 127, nb = (t >> 7) * 8;
        float bb = bl1[g];
        unsigned long long acc[4];
        unsigned long long bp = pk2(bb, bb);
        #pragma unroll
        for (int i = 0; i < 4; i++) acc[i] = bp;
        #pragma unroll 2
        for (int c = 0; c < 2 * HID; c++) {
            float wl = Wl1[c * HID + g];
            unsigned long long wp = pk2(wl, wl);
            const unsigned long long* row = (const unsigned long long*)&h2T[c][nb];
            #pragma unroll
            for (int i = 0; i < 4; i++) acc[i] = ffma2(row[i], wp, acc[i]);
        }
        #pragma unroll
        for (int i = 0; i < 4; i++) {
            float lo, hi; upk2(acc[i], lo, hi);
            h3sh[nb + 2 * i][g]     = fmaxf(lo, 0.f);
            h3sh[nb + 2 * i + 1][g] = fmaxf(hi, 0.f);
        }
    }
    __syncthreads();

    // phase 3: out[n] = h3[n] . Wl2 + bl2 ; warp per 2 nodes
    {
        int warp = t >> 5, lane = t & 31;
        #pragma unroll
        for (int rep = 0; rep < 2; rep++) {
            int n = warp * 2 + rep;
            int node = base + n;
            float s = 0.f;
            #pragma unroll
            for (int q = 0; q < 4; q++)
                s = fmaf(h3sh[n][lane + 32 * q], Wl2[lane + 32 * q], s);
            #pragma unroll
            for (int o = 16; o; o >>= 1) s += __shfl_xor_sync(0xFFFFFFFFu, s, o);
            if (lane == 0 && node < NN) out[node] = s + bl2[0];
        }
    }
}

// ---------------- launch ---------------------------------------------------------
extern "C" void kernel_launch(void* const* d_in, const int* in_sizes, int n_in,
                              void* d_out, int out_size) {
    const float* x   = (const float*)d_in[0];
    const void*  ei  = d_in[1];
    const float* w   = (const float*)d_in[2];
    const float* W1  = (const float*)d_in[3];
    const float* b1  = (const float*)d_in[4];
    const float* W2  = (const float*)d_in[5];
    const float* b2  = (const float*)d_in[6];
    const float* Wl1 = (const float*)d_in[7];
    const float* bl1 = (const float*)d_in[8];
    const float* Wl2 = (const float*)d_in[9];
    const float* bl2 = (const float*)d_in[10];
    float* out = (float*)d_out;

    const int TB = 256;
    const int EB = (NE + TB - 1) / TB;
    const int VB = (NN + TB - 1) / TB;

    k_init    <<<VB, TB>>>();
    k_conv_deg<<<EB, TB>>>(ei, w);
    k_scan    <<<NCHUNK, SCHUNK>>>();
    k_fill    <<<EB, TB>>>(w, x);
    k_expand  <<<(NN * 32 + TB - 1) / TB, TB>>>(x, W1, b1);
    k_agg     <<<(NN + 7) / 8, TB>>>();
    k_mlp     <<<(NN + NT - 1) / NT, TB>>>(W2, b2, Wl1, bl1, Wl2, bl2, out);
}